// round 3
// baseline (speedup 1.0000x reference)
#include <cuda_runtime.h>
#include <cstddef>

#define B_  8
#define T_  1024
#define D_  512
#define H_  8
#define KD_ 64
#define HK_ 512   // H_*KD_

// Scratch (device globals: allocation-free, graph-capture safe). 4 x 16.8 MB.
__device__ float g_qh[(size_t)B_ * T_ * HK_];
__device__ float g_kh[(size_t)B_ * T_ * HK_];
__device__ float g_vh[(size_t)B_ * T_ * HK_];
__device__ float g_attn[(size_t)B_ * T_ * HK_];

// ---------------------------------------------------------------------------
// Generic fp32 SGEMM: C[M,N] = A[M,K] @ W[K,N], all row-major.
// 128x128 block tile, BK=8, 256 threads, 8x8 micro-tile per thread.
// Requires M%128==0, N%128==0, K%8==0 (true for all our shapes).
// ---------------------------------------------------------------------------
__global__ __launch_bounds__(256, 2) void sgemm128(
    const float* __restrict__ A, const float* __restrict__ W,
    float* __restrict__ C, int M, int N, int K)
{
    __shared__ float As[8][128];   // As[k][m] (transposed A tile)
    __shared__ float Bs[8][128];   // Bs[k][n]

    const int tid  = threadIdx.x;
    const int bm   = blockIdx.y * 128;
    const int bn   = blockIdx.x * 128;
    const int arow = tid >> 1;            // 0..127
    const int acol = (tid & 1) << 2;      // 0 or 4
    const int brow = tid >> 5;            // 0..7
    const int bcol = (tid & 31) << 2;     // 0..124
    const int ty   = tid >> 4;            // 0..15
    const int tx   = tid & 15;            // 0..15

    float acc[8][8];
    #pragma unroll
    for (int i = 0; i < 8; i++)
        #pragma unroll
        for (int j = 0; j < 8; j++) acc[i][j] = 0.f;

    const float* Ap = A + (size_t)(bm + arow) * K + acol;
    const float* Bp = W + (size_t)brow * N + bn + bcol;

    for (int k0 = 0; k0 < K; k0 += 8) {
        float4 av = *(const float4*)Ap;
        float4 bv = *(const float4*)Bp;
        As[acol + 0][arow] = av.x;
        As[acol + 1][arow] = av.y;
        As[acol + 2][arow] = av.z;
        As[acol + 3][arow] = av.w;
        *(float4*)&Bs[brow][bcol] = bv;
        __syncthreads();

        #pragma unroll
        for (int k = 0; k < 8; k++) {
            float a[8], b[8];
            *(float4*)(a)     = *(const float4*)&As[k][ty * 8];
            *(float4*)(a + 4) = *(const float4*)&As[k][ty * 8 + 4];
            *(float4*)(b)     = *(const float4*)&Bs[k][tx * 8];
            *(float4*)(b + 4) = *(const float4*)&Bs[k][tx * 8 + 4];
            #pragma unroll
            for (int i = 0; i < 8; i++)
                #pragma unroll
                for (int j = 0; j < 8; j++)
                    acc[i][j] = fmaf(a[i], b[j], acc[i][j]);
        }
        __syncthreads();
        Ap += 8;
        Bp += (size_t)8 * N;
    }

    #pragma unroll
    for (int i = 0; i < 8; i++) {
        float* Cp = C + (size_t)(bm + ty * 8 + i) * N + bn + tx * 8;
        *(float4*)(Cp)     = make_float4(acc[i][0], acc[i][1], acc[i][2], acc[i][3]);
        *(float4*)(Cp + 4) = make_float4(acc[i][4], acc[i][5], acc[i][6], acc[i][7]);
    }
}

// ---------------------------------------------------------------------------
// Fused RBF attention per (b, h, query-block of 64):
//   S = Q K^T (over KD=64), W = exp(2S - |q|^2 - |k|^2)  -> written to gmem
//   A += W V   (accumulated across all 16 key blocks)    -> g_attn
// 256 threads; each thread owns a 4x4 micro-tile of the 64x64 S/W tile and of
// the 64x64 A accumulator.
// ---------------------------------------------------------------------------
#define QSTR 68   // padded smem stride (floats)

__global__ __launch_bounds__(256) void attn_kernel(float* __restrict__ wout)
{
    extern __shared__ float sm[];
    float* Qt = sm;                    // [64][QSTR]  Qt[d][r]
    float* Kt = Qt + 64 * QSTR;        // [64][QSTR]  Kt[d][c]
    float* Ws = Kt + 64 * QSTR;        // [64][QSTR]  Ws[r][c]
    float* Vs = Ws + 64 * QSTR;        // [64][64]    Vs[c][n]
    float* q2 = Vs + 64 * 64;          // [64]
    float* k2 = q2 + 64;               // [64]

    const int tid = threadIdx.x;
    const int b  = blockIdx.z;
    const int h  = blockIdx.y;
    const int qb = blockIdx.x;
    const int ty = tid >> 4, tx = tid & 15;
    const int lr = tid >> 2;           // tile row this thread loads (0..63)
    const int lc = (tid & 3) << 4;     // col base 0/16/32/48

    // --- load Q tile (transposed into Qt[d][r]) ---
    {
        const float* Qg = g_qh + (size_t)(b * T_ + qb * 64 + lr) * HK_ + h * KD_ + lc;
        #pragma unroll
        for (int c4 = 0; c4 < 16; c4 += 4) {
            float4 v = *(const float4*)(Qg + c4);
            Qt[(lc + c4 + 0) * QSTR + lr] = v.x;
            Qt[(lc + c4 + 1) * QSTR + lr] = v.y;
            Qt[(lc + c4 + 2) * QSTR + lr] = v.z;
            Qt[(lc + c4 + 3) * QSTR + lr] = v.w;
        }
    }
    __syncthreads();
    if (tid < 64) {
        float s = 0.f;
        #pragma unroll 8
        for (int d = 0; d < 64; d++) { float q = Qt[d * QSTR + tid]; s = fmaf(q, q, s); }
        q2[tid] = s;
    }

    float acc[4][4];
    #pragma unroll
    for (int i = 0; i < 4; i++)
        #pragma unroll
        for (int j = 0; j < 4; j++) acc[i][j] = 0.f;

    for (int kb = 0; kb < 16; kb++) {
        __syncthreads();   // protect Kt/Vs/Ws reuse (and q2 publish on kb==0)

        // --- load K (transposed) and V (natural) tiles ---
        {
            const float* Kg = g_kh + (size_t)(b * T_ + kb * 64 + lr) * HK_ + h * KD_ + lc;
            const float* Vg = g_vh + (size_t)(b * T_ + kb * 64 + lr) * HK_ + h * KD_ + lc;
            #pragma unroll
            for (int c4 = 0; c4 < 16; c4 += 4) {
                float4 kv = *(const float4*)(Kg + c4);
                Kt[(lc + c4 + 0) * QSTR + lr] = kv.x;
                Kt[(lc + c4 + 1) * QSTR + lr] = kv.y;
                Kt[(lc + c4 + 2) * QSTR + lr] = kv.z;
                Kt[(lc + c4 + 3) * QSTR + lr] = kv.w;
                *(float4*)&Vs[lr * 64 + lc + c4] = *(const float4*)(Vg + c4);
            }
        }
        __syncthreads();
        if (tid < 64) {
            float s = 0.f;
            #pragma unroll 8
            for (int d = 0; d < 64; d++) { float kk = Kt[d * QSTR + tid]; s = fmaf(kk, kk, s); }
            k2[tid] = s;
        }
        __syncthreads();

        // --- GEMM1: S = Q K^T over d ---
        float s[4][4];
        #pragma unroll
        for (int i = 0; i < 4; i++)
            #pragma unroll
            for (int j = 0; j < 4; j++) s[i][j] = 0.f;

        #pragma unroll 4
        for (int d = 0; d < 64; d++) {
            float4 a  = *(const float4*)&Qt[d * QSTR + ty * 4];
            float4 bb = *(const float4*)&Kt[d * QSTR + tx * 4];
            const float av[4] = {a.x, a.y, a.z, a.w};
            const float bv[4] = {bb.x, bb.y, bb.z, bb.w};
            #pragma unroll
            for (int i = 0; i < 4; i++)
                #pragma unroll
                for (int j = 0; j < 4; j++)
                    s[i][j] = fmaf(av[i], bv[j], s[i][j]);
        }

        // --- W = exp(2S - q2 - k2): write to gmem output and to smem for GEMM2 ---
        const float kk0 = k2[tx * 4 + 0];
        const float kk1 = k2[tx * 4 + 1];
        const float kk2 = k2[tx * 4 + 2];
        const float kk3 = k2[tx * 4 + 3];
        float* Wg = wout + ((size_t)(b * H_ + h) * T_ + (size_t)(qb * 64 + ty * 4)) * T_
                         + kb * 64 + tx * 4;
        #pragma unroll
        for (int i = 0; i < 4; i++) {
            const float qq = q2[ty * 4 + i];
            float4 w;
            w.x = __expf(fmaf(2.f, s[i][0], -(qq + kk0)));
            w.y = __expf(fmaf(2.f, s[i][1], -(qq + kk1)));
            w.z = __expf(fmaf(2.f, s[i][2], -(qq + kk2)));
            w.w = __expf(fmaf(2.f, s[i][3], -(qq + kk3)));
            *(float4*)&Ws[(ty * 4 + i) * QSTR + tx * 4] = w;
            *(float4*)(Wg + (size_t)i * T_) = w;
        }
        __syncthreads();

        // --- GEMM2: A += W V over key index c ---
        #pragma unroll 4
        for (int c = 0; c < 64; c++) {
            float4 bb = *(const float4*)&Vs[c * 64 + tx * 4];
            const float bv[4] = {bb.x, bb.y, bb.z, bb.w};
            float av[4];
            #pragma unroll
            for (int i = 0; i < 4; i++) av[i] = Ws[(ty * 4 + i) * QSTR + c];
            #pragma unroll
            for (int i = 0; i < 4; i++)
                #pragma unroll
                for (int j = 0; j < 4; j++)
                    acc[i][j] = fmaf(av[i], bv[j], acc[i][j]);
        }
    }

    // --- write A tile to g_attn [B*T, HK] ---
    #pragma unroll
    for (int i = 0; i < 4; i++) {
        float* Ap = g_attn + (size_t)(b * T_ + qb * 64 + ty * 4 + i) * HK_ + h * KD_ + tx * 4;
        *(float4*)Ap = make_float4(acc[i][0], acc[i][1], acc[i][2], acc[i][3]);
    }
}

// ---------------------------------------------------------------------------
extern "C" void kernel_launch(void* const* d_in, const int* in_sizes, int n_in,
                              void* d_out, int out_size)
{
    (void)in_sizes; (void)n_in; (void)out_size;
    const float* q  = (const float*)d_in[0];
    const float* k  = (const float*)d_in[1];
    const float* v  = (const float*)d_in[2];
    const float* Wq = (const float*)d_in[3];
    const float* Wk = (const float*)d_in[4];
    const float* Wv = (const float*)d_in[5];
    const float* Wo = (const float*)d_in[6];

    float* out    = (float*)d_out;                       // [B,T,D]
    float* attn_w = out + (size_t)B_ * T_ * D_;          // [B,H,T,T]

    float *p_qh, *p_kh, *p_vh, *p_attn;
    cudaGetSymbolAddress((void**)&p_qh,   g_qh);
    cudaGetSymbolAddress((void**)&p_kh,   g_kh);
    cudaGetSymbolAddress((void**)&p_vh,   g_vh);
    cudaGetSymbolAddress((void**)&p_attn, g_attn);

    const size_t SMEM = (size_t)(3 * 64 * QSTR + 64 * 64 + 128) * sizeof(float); // 69120 B
    cudaFuncSetAttribute(attn_kernel, cudaFuncAttributeMaxDynamicSharedMemorySize, (int)SMEM);

    dim3 gp(HK_ / 128, (B_ * T_) / 128);   // (4, 64)
    sgemm128<<<gp, 256>>>(q, Wq, p_qh, B_ * T_, HK_, D_);
    sgemm128<<<gp, 256>>>(k, Wk, p_kh, B_ * T_, HK_, D_);
    sgemm128<<<gp, 256>>>(v, Wv, p_vh, B_ * T_, HK_, D_);

    dim3 ga(T_ / 64, H_, B_);              // (16, 8, 8)
    attn_kernel<<<ga, 256, SMEM>>>(attn_w);

    dim3 go(D_ / 128, (B_ * T_) / 128);    // (4, 64)
    sgemm128<<<go, 256>>>(p_attn, Wo, out, B_ * T_, D_, HK_);
}

// round 10
// speedup vs baseline: 1.3713x; 1.3713x over previous
#include <cuda_runtime.h>
#include <cuda_bf16.h>
#include <cstdint>
#include <cstddef>

#define B_  8
#define T_  1024
#define D_  512
#define H_  8
#define KD_ 64
#define HK_ 512
#define KSPL 1536      // 3 * 512 (hi|lo|hi split-K)

// Scratch (device globals: allocation-free, graph-capture safe).
__device__ float g_qh[(size_t)B_ * T_ * HK_];
__device__ float g_kh[(size_t)B_ * T_ * HK_];
__device__ float g_vh[(size_t)B_ * T_ * HK_];
__device__ float g_attn[(size_t)B_ * T_ * HK_];
__device__ __nv_bfloat16 g_sA[(size_t)B_ * T_ * KSPL];   // split activations [8192][1536]
__device__ __nv_bfloat16 g_sW[(size_t)HK_ * KSPL];       // split+transposed weights [512][1536]

// ---------------------------------------------------------------------------
// Helpers (baseline sm_80+ features only: ldmatrix / mma.sync / cp.async)
// ---------------------------------------------------------------------------
__device__ __forceinline__ uint32_t smem_u32(const void* p) {
    uint32_t a;
    asm("{ .reg .u64 t; cvta.to.shared.u64 t, %1; cvt.u32.u64 %0, t; }" : "=r"(a) : "l"(p));
    return a;
}
__device__ __forceinline__ void ldsm4(uint32_t& r0, uint32_t& r1, uint32_t& r2, uint32_t& r3,
                                      uint32_t addr) {
    asm volatile("ldmatrix.sync.aligned.m8n8.x4.shared.b16 {%0,%1,%2,%3}, [%4];"
                 : "=r"(r0), "=r"(r1), "=r"(r2), "=r"(r3) : "r"(addr));
}
__device__ __forceinline__ void mma16816(float* d, const uint32_t* a, const uint32_t* b) {
    asm volatile(
        "mma.sync.aligned.m16n8k16.row.col.f32.bf16.bf16.f32 "
        "{%0,%1,%2,%3}, {%4,%5,%6,%7}, {%8,%9}, {%0,%1,%2,%3};"
        : "+f"(d[0]), "+f"(d[1]), "+f"(d[2]), "+f"(d[3])
        : "r"(a[0]), "r"(a[1]), "r"(a[2]), "r"(a[3]), "r"(b[0]), "r"(b[1]));
}
__device__ __forceinline__ void cpasync16(uint32_t dst, const void* src) {
    asm volatile("cp.async.cg.shared.global [%0], [%1], 16;" :: "r"(dst), "l"(src));
}

__device__ __forceinline__ void split1(float x, uint16_t& h, uint16_t& l) {
    __nv_bfloat16 bh = __float2bfloat16_rn(x);
    float r = x - __bfloat162float(bh);
    __nv_bfloat16 bl = __float2bfloat16_rn(r);
    h = __bfloat16_as_ushort(bh);
    l = __bfloat16_as_ushort(bl);
}

// ---------------------------------------------------------------------------
// split_act: X fp32 [8192][512] -> Y bf16 [8192][1536] = [hi | lo | hi]
// ---------------------------------------------------------------------------
__global__ __launch_bounds__(256) void split_act(const float* __restrict__ X,
                                                 __nv_bfloat16* __restrict__ Y) {
    size_t i = (size_t)blockIdx.x * 256 + threadIdx.x;   // over 8192*512/4
    float4 v = ((const float4*)X)[i];
    size_t row = i >> 7;
    int col = (int)((i & 127) << 2);
    uint16_t h0, h1, h2, h3, l0, l1, l2, l3;
    split1(v.x, h0, l0); split1(v.y, h1, l1); split1(v.z, h2, l2); split1(v.w, h3, l3);
    uint2 hp, lp;
    hp.x = (uint32_t)h0 | ((uint32_t)h1 << 16);
    hp.y = (uint32_t)h2 | ((uint32_t)h3 << 16);
    lp.x = (uint32_t)l0 | ((uint32_t)l1 << 16);
    lp.y = (uint32_t)l2 | ((uint32_t)l3 << 16);
    __nv_bfloat16* yr = Y + row * KSPL;
    *(uint2*)(yr + col)        = hp;
    *(uint2*)(yr + 512 + col)  = lp;
    *(uint2*)(yr + 1024 + col) = hp;
}

// ---------------------------------------------------------------------------
// split_wt: W fp32 [512 k][512 n] -> Yt bf16 [512 n][1536 k] = [hi | hi | lo]
// ---------------------------------------------------------------------------
__global__ __launch_bounds__(1024) void split_wt(const float* __restrict__ W,
                                                 __nv_bfloat16* __restrict__ Yt) {
    __shared__ float t[32][33];
    const int tx = threadIdx.x, ty = threadIdx.y;
    const int n0 = blockIdx.x * 32, k0 = blockIdx.y * 32;
    t[ty][tx] = W[(size_t)(k0 + ty) * 512 + n0 + tx];
    __syncthreads();
    float x = t[tx][ty];                       // = W[k0+tx][n0+ty]
    uint16_t h, l; split1(x, h, l);
    uint16_t* yr = (uint16_t*)(Yt + (size_t)(n0 + ty) * KSPL);
    yr[k0 + tx]        = h;
    yr[512 + k0 + tx]  = h;
    yr[1024 + k0 + tx] = l;
}

// ---------------------------------------------------------------------------
// mma.sync bf16 GEMM: C[8192][512] fp32 = A'[8192][1536] . Bt'[512][1536]^T
// 128x128 tile, BK=64, double-buffered cp.async, 8 warps x (64x32) warp tile.
// SMEM layout: row-major [128 rows][128 B], 16B chunk c stored at c ^ (row&7)
// -> conflict-free ldmatrix & conflict-free stores.
// ---------------------------------------------------------------------------
#define NCH 24   // 1536 / 64

__global__ __launch_bounds__(256) void gemm_mma(
    const __nv_bfloat16* __restrict__ A,
    const __nv_bfloat16* __restrict__ Bt,
    float* __restrict__ C)
{
    extern __shared__ char sm[];
    const uint32_t smb = smem_u32(sm);
    // buffers: A: [2][16KB] at 0, B: [2][16KB] at 32KB
    const int tid = threadIdx.x, lane = tid & 31, wid = tid >> 5;
    const int wm = (wid >> 2) * 64;   // 0 / 64
    const int wn = (wid & 3) * 32;    // 0/32/64/96
    const int tm = blockIdx.y, tn = blockIdx.x;

    const __nv_bfloat16* Ag = A  + (size_t)(tm * 128) * KSPL;
    const __nv_bfloat16* Bg = Bt + (size_t)(tn * 128) * KSPL;

    // per-thread global-load coords: chunk u = tid + it*256; row=u>>3, c=u&7
    float acc[4][4][4];
    #pragma unroll
    for (int i = 0; i < 4; i++)
        #pragma unroll
        for (int j = 0; j < 4; j++)
            #pragma unroll
            for (int r = 0; r < 4; r++) acc[i][j][r] = 0.f;

    // prologue: chunk 0 -> buf 0
    {
        #pragma unroll
        for (int it = 0; it < 4; it++) {
            int u = tid + it * 256, row = u >> 3, c = u & 7;
            uint32_t d = (uint32_t)(row * 128 + ((c ^ (row & 7)) << 4));
            cpasync16(smb + d,           Ag + (size_t)row * KSPL + c * 8);
            cpasync16(smb + 32768 + d,   Bg + (size_t)row * KSPL + c * 8);
        }
        asm volatile("cp.async.commit_group;");
    }

    for (int ch = 0; ch < NCH; ch++) {
        const int buf = ch & 1;
        if (ch + 1 < NCH) {
            const int nb = (ch + 1) & 1;
            const int ko = (ch + 1) * 64;
            #pragma unroll
            for (int it = 0; it < 4; it++) {
                int u = tid + it * 256, row = u >> 3, c = u & 7;
                uint32_t d = (uint32_t)(nb * 16384 + row * 128 + ((c ^ (row & 7)) << 4));
                cpasync16(smb + d,         Ag + (size_t)row * KSPL + ko + c * 8);
                cpasync16(smb + 32768 + d, Bg + (size_t)row * KSPL + ko + c * 8);
            }
            asm volatile("cp.async.commit_group;");
            asm volatile("cp.async.wait_group 1;");
        } else {
            asm volatile("cp.async.wait_group 0;");
        }
        __syncthreads();

        const uint32_t sA = smb + buf * 16384;
        const uint32_t sB = smb + 32768 + buf * 16384;

        #pragma unroll
        for (int ks = 0; ks < 4; ks++) {
            const int c0 = ks * 2;
            uint32_t aF[4][4], bF[4][2];
            #pragma unroll
            for (int i = 0; i < 4; i++) {
                int m = wm + i * 16 + ((lane >> 3) & 1) * 8 + (lane & 7);
                int c = c0 + (lane >> 4);
                ldsm4(aF[i][0], aF[i][1], aF[i][2], aF[i][3],
                      sA + m * 128 + ((c ^ (m & 7)) << 4));
            }
            #pragma unroll
            for (int jj = 0; jj < 2; jj++) {
                int n = wn + jj * 16 + ((lane >> 4)) * 8 + (lane & 7);
                int c = c0 + ((lane >> 3) & 1);
                uint32_t r0, r1, r2, r3;
                ldsm4(r0, r1, r2, r3, sB + n * 128 + ((c ^ (n & 7)) << 4));
                bF[jj * 2 + 0][0] = r0; bF[jj * 2 + 0][1] = r1;
                bF[jj * 2 + 1][0] = r2; bF[jj * 2 + 1][1] = r3;
            }
            #pragma unroll
            for (int i = 0; i < 4; i++)
                #pragma unroll
                for (int j = 0; j < 4; j++)
                    mma16816(acc[i][j], aF[i], bF[j]);
        }
        __syncthreads();
    }

    // epilogue: thread holds rows (lane>>2){+0,+8}, cols (lane&3)*2
    #pragma unroll
    for (int i = 0; i < 4; i++) {
        int row0 = tm * 128 + wm + i * 16 + (lane >> 2);
        #pragma unroll
        for (int j = 0; j < 4; j++) {
            int col = tn * 128 + wn + j * 8 + (lane & 3) * 2;
            *(float2*)(C + (size_t)row0 * 512 + col)       = make_float2(acc[i][j][0], acc[i][j][1]);
            *(float2*)(C + (size_t)(row0 + 8) * 512 + col) = make_float2(acc[i][j][2], acc[i][j][3]);
        }
    }
}

// ---------------------------------------------------------------------------
// Fused RBF attention (unchanged R3 baseline; SIMT fp32).
// ---------------------------------------------------------------------------
#define QSTR 68

__global__ __launch_bounds__(256) void attn_kernel(float* __restrict__ wout)
{
    extern __shared__ float smf[];
    float* Qt = smf;
    float* Kt = Qt + 64 * QSTR;
    float* Ws = Kt + 64 * QSTR;
    float* Vs = Ws + 64 * QSTR;
    float* q2 = Vs + 64 * 64;
    float* k2 = q2 + 64;

    const int tid = threadIdx.x;
    const int b = blockIdx.z, h = blockIdx.y, qb = blockIdx.x;
    const int ty = tid >> 4, tx = tid & 15;
    const int lr = tid >> 2;
    const int lc = (tid & 3) << 4;

    {
        const float* Qg = g_qh + (size_t)(b * T_ + qb * 64 + lr) * HK_ + h * KD_ + lc;
        #pragma unroll
        for (int c4 = 0; c4 < 16; c4 += 4) {
            float4 v = *(const float4*)(Qg + c4);
            Qt[(lc + c4 + 0) * QSTR + lr] = v.x;
            Qt[(lc + c4 + 1) * QSTR + lr] = v.y;
            Qt[(lc + c4 + 2) * QSTR + lr] = v.z;
            Qt[(lc + c4 + 3) * QSTR + lr] = v.w;
        }
    }
    __syncthreads();
    if (tid < 64) {
        float s = 0.f;
        #pragma unroll 8
        for (int d = 0; d < 64; d++) { float q = Qt[d * QSTR + tid]; s = fmaf(q, q, s); }
        q2[tid] = s;
    }

    float acc[4][4];
    #pragma unroll
    for (int i = 0; i < 4; i++)
        #pragma unroll
        for (int j = 0; j < 4; j++) acc[i][j] = 0.f;

    for (int kb = 0; kb < 16; kb++) {
        __syncthreads();
        {
            const float* Kg = g_kh + (size_t)(b * T_ + kb * 64 + lr) * HK_ + h * KD_ + lc;
            const float* Vg = g_vh + (size_t)(b * T_ + kb * 64 + lr) * HK_ + h * KD_ + lc;
            #pragma unroll
            for (int c4 = 0; c4 < 16; c4 += 4) {
                float4 kv = *(const float4*)(Kg + c4);
                Kt[(lc + c4 + 0) * QSTR + lr] = kv.x;
                Kt[(lc + c4 + 1) * QSTR + lr] = kv.y;
                Kt[(lc + c4 + 2) * QSTR + lr] = kv.z;
                Kt[(lc + c4 + 3) * QSTR + lr] = kv.w;
                *(float4*)&Vs[lr * 64 + lc + c4] = *(const float4*)(Vg + c4);
            }
        }
        __syncthreads();
        if (tid < 64) {
            float s = 0.f;
            #pragma unroll 8
            for (int d = 0; d < 64; d++) { float kk = Kt[d * QSTR + tid]; s = fmaf(kk, kk, s); }
            k2[tid] = s;
        }
        __syncthreads();

        float s[4][4];
        #pragma unroll
        for (int i = 0; i < 4; i++)
            #pragma unroll
            for (int j = 0; j < 4; j++) s[i][j] = 0.f;

        #pragma unroll 4
        for (int d = 0; d < 64; d++) {
            float4 a  = *(const float4*)&Qt[d * QSTR + ty * 4];
            float4 bb = *(const float4*)&Kt[d * QSTR + tx * 4];
            const float av[4] = {a.x, a.y, a.z, a.w};
            const float bv[4] = {bb.x, bb.y, bb.z, bb.w};
            #pragma unroll
            for (int i = 0; i < 4; i++)
                #pragma unroll
                for (int j = 0; j < 4; j++)
                    s[i][j] = fmaf(av[i], bv[j], s[i][j]);
        }

        const float kk0 = k2[tx * 4 + 0];
        const float kk1 = k2[tx * 4 + 1];
        const float kk2 = k2[tx * 4 + 2];
        const float kk3 = k2[tx * 4 + 3];
        float* Wg = wout + ((size_t)(b * H_ + h) * T_ + (size_t)(qb * 64 + ty * 4)) * T_
                         + kb * 64 + tx * 4;
        #pragma unroll
        for (int i = 0; i < 4; i++) {
            const float qq = q2[ty * 4 + i];
            float4 w;
            w.x = __expf(fmaf(2.f, s[i][0], -(qq + kk0)));
            w.y = __expf(fmaf(2.f, s[i][1], -(qq + kk1)));
            w.z = __expf(fmaf(2.f, s[i][2], -(qq + kk2)));
            w.w = __expf(fmaf(2.f, s[i][3], -(qq + kk3)));
            *(float4*)&Ws[(ty * 4 + i) * QSTR + tx * 4] = w;
            *(float4*)(Wg + (size_t)i * T_) = w;
        }
        __syncthreads();

        #pragma unroll 4
        for (int c = 0; c < 64; c++) {
            float4 bb = *(const float4*)&Vs[c * 64 + tx * 4];
            const float bv[4] = {bb.x, bb.y, bb.z, bb.w};
            float av[4];
            #pragma unroll
            for (int i = 0; i < 4; i++) av[i] = Ws[(ty * 4 + i) * QSTR + c];
            #pragma unroll
            for (int i = 0; i < 4; i++)
                #pragma unroll
                for (int j = 0; j < 4; j++)
                    acc[i][j] = fmaf(av[i], bv[j], acc[i][j]);
        }
    }

    #pragma unroll
    for (int i = 0; i < 4; i++) {
        float* Ap = g_attn + (size_t)(b * T_ + qb * 64 + ty * 4 + i) * HK_ + h * KD_ + tx * 4;
        *(float4*)Ap = make_float4(acc[i][0], acc[i][1], acc[i][2], acc[i][3]);
    }
}

// ---------------------------------------------------------------------------
extern "C" void kernel_launch(void* const* d_in, const int* in_sizes, int n_in,
                              void* d_out, int out_size)
{
    (void)in_sizes; (void)n_in; (void)out_size;
    const float* q  = (const float*)d_in[0];
    const float* k  = (const float*)d_in[1];
    const float* v  = (const float*)d_in[2];
    const float* Wq = (const float*)d_in[3];
    const float* Wk = (const float*)d_in[4];
    const float* Wv = (const float*)d_in[5];
    const float* Wo = (const float*)d_in[6];

    float* out    = (float*)d_out;
    float* attn_w = out + (size_t)B_ * T_ * D_;

    float *p_qh, *p_kh, *p_vh, *p_attn;
    __nv_bfloat16 *p_sA, *p_sW;
    cudaGetSymbolAddress((void**)&p_qh,   g_qh);
    cudaGetSymbolAddress((void**)&p_kh,   g_kh);
    cudaGetSymbolAddress((void**)&p_vh,   g_vh);
    cudaGetSymbolAddress((void**)&p_attn, g_attn);
    cudaGetSymbolAddress((void**)&p_sA,   g_sA);
    cudaGetSymbolAddress((void**)&p_sW,   g_sW);

    const size_t ASMEM = (size_t)(3 * 64 * QSTR + 64 * 64 + 128) * sizeof(float);
    cudaFuncSetAttribute(attn_kernel, cudaFuncAttributeMaxDynamicSharedMemorySize, (int)ASMEM);
    cudaFuncSetAttribute(gemm_mma,   cudaFuncAttributeMaxDynamicSharedMemorySize, 65536);

    const dim3 gsplit(4096), bsplit(256);
    const dim3 gwt(16, 16), bwt(32, 32);
    const dim3 ggemm(4, 64), bgemm(256);

    // Q projection
    split_act<<<gsplit, bsplit>>>(q, p_sA);
    split_wt<<<gwt, bwt>>>(Wq, p_sW);
    gemm_mma<<<ggemm, bgemm, 65536>>>(p_sA, p_sW, p_qh);
    // K projection
    split_act<<<gsplit, bsplit>>>(k, p_sA);
    split_wt<<<gwt, bwt>>>(Wk, p_sW);
    gemm_mma<<<ggemm, bgemm, 65536>>>(p_sA, p_sW, p_kh);
    // V projection
    split_act<<<gsplit, bsplit>>>(v, p_sA);
    split_wt<<<gwt, bwt>>>(Wv, p_sW);
    gemm_mma<<<ggemm, bgemm, 65536>>>(p_sA, p_sW, p_vh);

    // Attention (writes attn_w and g_attn)
    attn_kernel<<<dim3(T_ / 64, H_, B_), 256, ASMEM>>>(attn_w);

    // Output projection
    split_act<<<gsplit, bsplit>>>(p_attn, p_sA);
    split_wt<<<gwt, bwt>>>(Wo, p_sW);
    gemm_mma<<<ggemm, bgemm, 65536>>>(p_sA, p_sW, out);
}

// round 13
// speedup vs baseline: 1.8211x; 1.3280x over previous
#include <cuda_runtime.h>
#include <cuda_bf16.h>
#include <cstdint>
#include <cstddef>

#define B_  8
#define T_  1024
#define D_  512
#define H_  8
#define KD_ 64
#define HK_ 512
#define KSPL 1536      // 3 * 512 (hi|lo|hi split-K for projection GEMMs)

// Scratch (device globals: allocation-free, graph-capture safe).
__device__ float g_qh[(size_t)B_ * T_ * HK_];
__device__ float g_kh[(size_t)B_ * T_ * HK_];
__device__ float g_vh[(size_t)B_ * T_ * HK_];
__device__ float g_attn[(size_t)B_ * T_ * HK_];
__device__ __nv_bfloat16 g_sA[(size_t)B_ * T_ * KSPL];      // split activations [8192][1536]
__device__ __nv_bfloat16 g_sW[(size_t)HK_ * KSPL];          // split weights [512][1536]
__device__ __nv_bfloat16 g_sQ[(size_t)B_ * H_ * T_ * 192];  // per-head split Q [BH][1024][192]
__device__ __nv_bfloat16 g_sK[(size_t)B_ * H_ * T_ * 192];  // per-head split K
__device__ __nv_bfloat16 g_sV[(size_t)B_ * H_ * 128 * T_];  // per-head V^T split [BH][128(d hi|lo)][1024]
__device__ float g_q2[(size_t)B_ * H_ * T_];
__device__ float g_k2[(size_t)B_ * H_ * T_];

// ---------------------------------------------------------------------------
// Helpers (baseline sm_80+ features: ldmatrix / mma.sync / cp.async)
// ---------------------------------------------------------------------------
__device__ __forceinline__ uint32_t smem_u32(const void* p) {
    uint32_t a;
    asm("{ .reg .u64 t; cvta.to.shared.u64 t, %1; cvt.u32.u64 %0, t; }" : "=r"(a) : "l"(p));
    return a;
}
__device__ __forceinline__ void ldsm4(uint32_t& r0, uint32_t& r1, uint32_t& r2, uint32_t& r3,
                                      uint32_t addr) {
    asm volatile("ldmatrix.sync.aligned.m8n8.x4.shared.b16 {%0,%1,%2,%3}, [%4];"
                 : "=r"(r0), "=r"(r1), "=r"(r2), "=r"(r3) : "r"(addr));
}
__device__ __forceinline__ void mma16816(float* d, const uint32_t* a, const uint32_t* b) {
    asm volatile(
        "mma.sync.aligned.m16n8k16.row.col.f32.bf16.bf16.f32 "
        "{%0,%1,%2,%3}, {%4,%5,%6,%7}, {%8,%9}, {%0,%1,%2,%3};"
        : "+f"(d[0]), "+f"(d[1]), "+f"(d[2]), "+f"(d[3])
        : "r"(a[0]), "r"(a[1]), "r"(a[2]), "r"(a[3]), "r"(b[0]), "r"(b[1]));
}
__device__ __forceinline__ void cpasync16(uint32_t dst, const void* src) {
    asm volatile("cp.async.cg.shared.global [%0], [%1], 16;" :: "r"(dst), "l"(src));
}
__device__ __forceinline__ uint32_t packbf(float lo, float hi) {   // low half <- lo
    uint32_t r;
    asm("cvt.rn.bf16x2.f32 %0, %1, %2;" : "=r"(r) : "f"(hi), "f"(lo));
    return r;
}
__device__ __forceinline__ void split1(float x, uint16_t& h, uint16_t& l) {
    __nv_bfloat16 bh = __float2bfloat16_rn(x);
    float r = x - __bfloat162float(bh);
    __nv_bfloat16 bl = __float2bfloat16_rn(r);
    h = __bfloat16_as_ushort(bh);
    l = __bfloat16_as_ushort(bl);
}

// ---------------------------------------------------------------------------
// split_act: X fp32 [8192][512] -> Y bf16 [8192][1536] = [hi | lo | hi]
// ---------------------------------------------------------------------------
__global__ __launch_bounds__(256) void split_act(const float* __restrict__ X,
                                                 __nv_bfloat16* __restrict__ Y) {
    size_t i = (size_t)blockIdx.x * 256 + threadIdx.x;
    float4 v = ((const float4*)X)[i];
    size_t row = i >> 7;
    int col = (int)((i & 127) << 2);
    uint16_t h0, h1, h2, h3, l0, l1, l2, l3;
    split1(v.x, h0, l0); split1(v.y, h1, l1); split1(v.z, h2, l2); split1(v.w, h3, l3);
    uint2 hp, lp;
    hp.x = (uint32_t)h0 | ((uint32_t)h1 << 16);
    hp.y = (uint32_t)h2 | ((uint32_t)h3 << 16);
    lp.x = (uint32_t)l0 | ((uint32_t)l1 << 16);
    lp.y = (uint32_t)l2 | ((uint32_t)l3 << 16);
    __nv_bfloat16* yr = Y + row * KSPL;
    *(uint2*)(yr + col)        = hp;
    *(uint2*)(yr + 512 + col)  = lp;
    *(uint2*)(yr + 1024 + col) = hp;
}

// ---------------------------------------------------------------------------
// split_wt: W fp32 [512 k][512 n] -> Yt bf16 [512 n][1536 k] = [hi | hi | lo]
// ---------------------------------------------------------------------------
__global__ __launch_bounds__(1024) void split_wt(const float* __restrict__ W,
                                                 __nv_bfloat16* __restrict__ Yt) {
    __shared__ float t[32][33];
    const int tx = threadIdx.x, ty = threadIdx.y;
    const int n0 = blockIdx.x * 32, k0 = blockIdx.y * 32;
    t[ty][tx] = W[(size_t)(k0 + ty) * 512 + n0 + tx];
    __syncthreads();
    float x = t[tx][ty];
    uint16_t h, l; split1(x, h, l);
    uint16_t* yr = (uint16_t*)(Yt + (size_t)(n0 + ty) * KSPL);
    yr[k0 + tx]        = h;
    yr[512 + k0 + tx]  = h;
    yr[1024 + k0 + tx] = l;
}

// ---------------------------------------------------------------------------
// mma.sync bf16 GEMM (validated R10): C[8192][512] = A'[8192][1536]·Bt'^T
// ---------------------------------------------------------------------------
#define NCH 24

__global__ __launch_bounds__(256) void gemm_mma(
    const __nv_bfloat16* __restrict__ A,
    const __nv_bfloat16* __restrict__ Bt,
    float* __restrict__ C)
{
    extern __shared__ char sm[];
    const uint32_t smb = smem_u32(sm);
    const int tid = threadIdx.x, lane = tid & 31, wid = tid >> 5;
    const int wm = (wid >> 2) * 64;
    const int wn = (wid & 3) * 32;
    const int tm = blockIdx.y, tn = blockIdx.x;

    const __nv_bfloat16* Ag = A  + (size_t)(tm * 128) * KSPL;
    const __nv_bfloat16* Bg = Bt + (size_t)(tn * 128) * KSPL;

    float acc[4][4][4];
    #pragma unroll
    for (int i = 0; i < 4; i++)
        #pragma unroll
        for (int j = 0; j < 4; j++)
            #pragma unroll
            for (int r = 0; r < 4; r++) acc[i][j][r] = 0.f;

    {
        #pragma unroll
        for (int it = 0; it < 4; it++) {
            int u = tid + it * 256, row = u >> 3, c = u & 7;
            uint32_t d = (uint32_t)(row * 128 + ((c ^ (row & 7)) << 4));
            cpasync16(smb + d,           Ag + (size_t)row * KSPL + c * 8);
            cpasync16(smb + 32768 + d,   Bg + (size_t)row * KSPL + c * 8);
        }
        asm volatile("cp.async.commit_group;");
    }

    for (int ch = 0; ch < NCH; ch++) {
        const int buf = ch & 1;
        if (ch + 1 < NCH) {
            const int nb = (ch + 1) & 1;
            const int ko = (ch + 1) * 64;
            #pragma unroll
            for (int it = 0; it < 4; it++) {
                int u = tid + it * 256, row = u >> 3, c = u & 7;
                uint32_t d = (uint32_t)(nb * 16384 + row * 128 + ((c ^ (row & 7)) << 4));
                cpasync16(smb + d,         Ag + (size_t)row * KSPL + ko + c * 8);
                cpasync16(smb + 32768 + d, Bg + (size_t)row * KSPL + ko + c * 8);
            }
            asm volatile("cp.async.commit_group;");
            asm volatile("cp.async.wait_group 1;");
        } else {
            asm volatile("cp.async.wait_group 0;");
        }
        __syncthreads();

        const uint32_t sA = smb + buf * 16384;
        const uint32_t sB = smb + 32768 + buf * 16384;

        #pragma unroll
        for (int ks = 0; ks < 4; ks++) {
            const int c0 = ks * 2;
            uint32_t aF[4][4], bF[4][2];
            #pragma unroll
            for (int i = 0; i < 4; i++) {
                int m = wm + i * 16 + ((lane >> 3) & 1) * 8 + (lane & 7);
                int c = c0 + (lane >> 4);
                ldsm4(aF[i][0], aF[i][1], aF[i][2], aF[i][3],
                      sA + m * 128 + ((c ^ (m & 7)) << 4));
            }
            #pragma unroll
            for (int jj = 0; jj < 2; jj++) {
                int n = wn + jj * 16 + ((lane >> 4)) * 8 + (lane & 7);
                int c = c0 + ((lane >> 3) & 1);
                uint32_t r0, r1, r2, r3;
                ldsm4(r0, r1, r2, r3, sB + n * 128 + ((c ^ (n & 7)) << 4));
                bF[jj * 2 + 0][0] = r0; bF[jj * 2 + 0][1] = r1;
                bF[jj * 2 + 1][0] = r2; bF[jj * 2 + 1][1] = r3;
            }
            #pragma unroll
            for (int i = 0; i < 4; i++)
                #pragma unroll
                for (int j = 0; j < 4; j++)
                    mma16816(acc[i][j], aF[i], bF[j]);
        }
        __syncthreads();
    }

    #pragma unroll
    for (int i = 0; i < 4; i++) {
        int row0 = tm * 128 + wm + i * 16 + (lane >> 2);
        #pragma unroll
        for (int j = 0; j < 4; j++) {
            int col = tn * 128 + wn + j * 8 + (lane & 3) * 2;
            *(float2*)(C + (size_t)row0 * 512 + col)       = make_float2(acc[i][j][0], acc[i][j][1]);
            *(float2*)(C + (size_t)(row0 + 8) * 512 + col) = make_float2(acc[i][j][2], acc[i][j][3]);
        }
    }
}

// ---------------------------------------------------------------------------
// split_qk: per-head split of qh/kh fp32 -> [BH][1024][192] bf16 + |x|^2.
// kmode=0 (Q): [hi|lo|hi]; kmode=1 (K): [hi|hi|lo].
// ---------------------------------------------------------------------------
__global__ __launch_bounds__(256) void split_qk(const float* __restrict__ X,
                                                __nv_bfloat16* __restrict__ Y,
                                                float* __restrict__ sq, int kmode) {
    __shared__ float red[4][64];
    const int b = blockIdx.z, h = blockIdx.y;
    const int tr = threadIdx.x >> 6, dh = threadIdx.x & 63;
    const int t = blockIdx.x * 4 + tr;
    float x = X[((size_t)(b * 1024 + t)) * 512 + h * 64 + dh];
    uint16_t hi, lo; split1(x, hi, lo);
    uint16_t* yr = (uint16_t*)Y + ((size_t)((b * 8 + h) * 1024 + t)) * 192;
    yr[dh] = hi;
    if (kmode) { yr[64 + dh] = hi; yr[128 + dh] = lo; }
    else       { yr[64 + dh] = lo; yr[128 + dh] = hi; }
    red[tr][dh] = x * x;
    __syncthreads();
    if (dh == 0) {
        float s = 0.f;
        #pragma unroll 8
        for (int i = 0; i < 64; i++) s += red[tr][i];
        sq[(size_t)(b * 8 + h) * 1024 + t] = s;
    }
}

// ---------------------------------------------------------------------------
// split_v: vh fp32 [B*T][512] -> g_sV bf16 [BH][128][1024]  (V^T, rows=d hi|lo)
// ---------------------------------------------------------------------------
__global__ void split_v(const float* __restrict__ X, __nv_bfloat16* __restrict__ Y) {
    __shared__ float t32[32][33];
    const int tx = threadIdx.x, ty = threadIdx.y;
    const int Tb = blockIdx.x * 32, Cb = blockIdx.y * 32, b = blockIdx.z;
    t32[ty][tx] = X[((size_t)(b * 1024 + Tb + ty)) * 512 + Cb + tx];
    __syncthreads();
    float val = t32[tx][ty];                 // element (t = Tb+tx, col = Cb+ty)
    const int col = Cb + ty;
    const int h = col >> 6, dh = col & 63;
    uint16_t hi, lo; split1(val, hi, lo);
    uint16_t* yp = (uint16_t*)Y;
    size_t base = ((size_t)(b * 8 + h) * 128 + dh) * 1024 + Tb + tx;
    yp[base]              = hi;
    yp[base + 64 * 1024]  = lo;
}

// ---------------------------------------------------------------------------
// Fused RBF attention on mma.sync.
// Grid (T/128, H, B), 256 threads (8 warps, warp w owns q-rows 16w..16w+16).
// Per k-block (128): S = Q'K'^T (K'=192 split); W = exp(2S - q2 - k2) -> gmem;
// A += Whi*Vhi + Whi*Vlo + Wlo*Vhi  (V^T in smem rows d: 0-63 hi, 64-127 lo).
// ---------------------------------------------------------------------------
#define SQ_OFF 0
#define SK_OFF 49152
#define SV_OFF 147456
#define AT_SMEM 212992   // 48K Q + 2*48K K + 2*32K V + pad

__global__ __launch_bounds__(256) void attn_mma(float* __restrict__ wout)
{
    extern __shared__ char sm[];
    const uint32_t smb = smem_u32(sm);
    const int tid = threadIdx.x, lane = tid & 31, w = tid >> 5;
    const int qb = blockIdx.x, h = blockIdx.y, b = blockIdx.z;
    const int bh = b * 8 + h;

    const char* Qg = (const char*)(g_sQ + ((size_t)bh * 1024 + qb * 128) * 192);
    const char* Kg = (const char*)(g_sK + (size_t)bh * 1024 * 192);
    const char* Vg = (const char*)(g_sV + (size_t)bh * 128 * 1024);

    const int lrow = tid >> 1;   // 0..127 (cooperative load row)

    // prologue: Q tile + KV(0) in one cp.async group
    #pragma unroll
    for (int i = 0; i < 12; i++) {
        int c = (tid & 1) * 12 + i;
        cpasync16(smb + SQ_OFF + lrow * 384 + ((c ^ (lrow & 7)) << 4),
                  Qg + (size_t)lrow * 384 + c * 16);
        cpasync16(smb + SK_OFF + lrow * 384 + ((c ^ (lrow & 7)) << 4),
                  Kg + (size_t)lrow * 384 + c * 16);
    }
    #pragma unroll
    for (int i = 0; i < 8; i++) {
        int c = (tid & 1) * 8 + i;
        cpasync16(smb + SV_OFF + lrow * 256 + ((c ^ (lrow & 7)) << 4),
                  Vg + (size_t)lrow * 2048 + c * 16);
    }
    asm volatile("cp.async.commit_group;");

    const int rq = qb * 128 + 16 * w + (lane >> 2);          // q row (global in T)
    const float q2a = g_q2[(size_t)bh * 1024 + rq];
    const float q2b = g_q2[(size_t)bh * 1024 + rq + 8];
    const float* k2p = g_k2 + (size_t)bh * 1024;

    float acc2[8][4];
    #pragma unroll
    for (int j = 0; j < 8; j++)
        #pragma unroll
        for (int r = 0; r < 4; r++) acc2[j][r] = 0.f;

    for (int kb = 0; kb < 8; kb++) {
        const int buf = kb & 1;
        if (kb < 7) {
            const int nb = (kb + 1) & 1;
            #pragma unroll
            for (int i = 0; i < 12; i++) {
                int c = (tid & 1) * 12 + i;
                cpasync16(smb + SK_OFF + nb * 49152 + lrow * 384 + ((c ^ (lrow & 7)) << 4),
                          Kg + (size_t)((kb + 1) * 128 + lrow) * 384 + c * 16);
            }
            #pragma unroll
            for (int i = 0; i < 8; i++) {
                int c = (tid & 1) * 8 + i;
                cpasync16(smb + SV_OFF + nb * 32768 + lrow * 256 + ((c ^ (lrow & 7)) << 4),
                          Vg + (size_t)lrow * 2048 + (kb + 1) * 256 + c * 16);
            }
            asm volatile("cp.async.commit_group;");
            asm volatile("cp.async.wait_group 1;");
        } else {
            asm volatile("cp.async.wait_group 0;");
        }
        __syncthreads();

        const uint32_t sKb = smb + SK_OFF + buf * 49152;
        const uint32_t sVb = smb + SV_OFF + buf * 32768;

        // ---- GEMM1: S[16 x 128] over K'=192 ----
        float sfr[16][4];
        #pragma unroll
        for (int f = 0; f < 16; f++)
            #pragma unroll
            for (int r = 0; r < 4; r++) sfr[f][r] = 0.f;

        #pragma unroll
        for (int ks = 0; ks < 12; ks++) {
            uint32_t a[4];
            {
                int m = 16 * w + (lane & 7) + ((lane >> 3) & 1) * 8;
                int c = 2 * ks + (lane >> 4);
                ldsm4(a[0], a[1], a[2], a[3], smb + SQ_OFF + m * 384 + ((c ^ (m & 7)) << 4));
            }
            #pragma unroll
            for (int j = 0; j < 8; j++) {
                int n = j * 16 + ((lane >> 4)) * 8 + (lane & 7);
                int c = 2 * ks + ((lane >> 3) & 1);
                uint32_t r0, r1, r2, r3;
                ldsm4(r0, r1, r2, r3, sKb + n * 384 + ((c ^ (n & 7)) << 4));
                uint32_t b01[2] = {r0, r1}, b23[2] = {r2, r3};
                mma16816(sfr[2 * j],     a, b01);
                mma16816(sfr[2 * j + 1], a, b23);
            }
        }

        // ---- exp epilogue: W to gmem + packed Whi/Wlo for GEMM2 ----
        uint32_t whi[16][2], wlo[16][2];
        const size_t wbase = ((size_t)bh * 1024 + rq) * 1024 + kb * 128 + (lane & 3) * 2;
        #pragma unroll
        for (int c = 0; c < 16; c++) {
            const int colk = kb * 128 + 8 * c + (lane & 3) * 2;
            const float k2x = k2p[colk], k2y = k2p[colk + 1];
            float w0 = __expf(fmaf(2.f, sfr[c][0], -(q2a + k2x)));
            float w1 = __expf(fmaf(2.f, sfr[c][1], -(q2a + k2y)));
            float w2 = __expf(fmaf(2.f, sfr[c][2], -(q2b + k2x)));
            float w3 = __expf(fmaf(2.f, sfr[c][3], -(q2b + k2y)));
            *(float2*)(wout + wbase + 8 * c)                       = make_float2(w0, w1);
            *(float2*)(wout + wbase + 8 * c + (size_t)8 * 1024)    = make_float2(w2, w3);
            uint32_t h01 = packbf(w0, w1);
            uint32_t h23 = packbf(w2, w3);
            float l0 = w0 - __uint_as_float(h01 << 16);
            float l1 = w1 - __uint_as_float(h01 & 0xFFFF0000u);
            float l2 = w2 - __uint_as_float(h23 << 16);
            float l3 = w3 - __uint_as_float(h23 & 0xFFFF0000u);
            whi[c][0] = h01; whi[c][1] = h23;
            wlo[c][0] = packbf(l0, l1);
            wlo[c][1] = packbf(l2, l3);
        }

        // ---- GEMM2: A += Whi*Vhi + Whi*Vlo + Wlo*Vhi ----
        #pragma unroll
        for (int s = 0; s < 8; s++) {
            uint32_t aH[4] = {whi[2 * s][0], whi[2 * s][1], whi[2 * s + 1][0], whi[2 * s + 1][1]};
            uint32_t aL[4] = {wlo[2 * s][0], wlo[2 * s][1], wlo[2 * s + 1][0], wlo[2 * s + 1][1]};
            #pragma unroll
            for (int j = 0; j < 4; j++) {
                int nh = j * 16 + ((lane >> 4)) * 8 + (lane & 7);
                int cb = 2 * s + ((lane >> 3) & 1);
                uint32_t h0, h1, h2, h3, l0, l1, l2, l3;
                ldsm4(h0, h1, h2, h3, sVb + nh * 256 + ((cb ^ (nh & 7)) << 4));
                int nl = nh + 64;
                ldsm4(l0, l1, l2, l3, sVb + nl * 256 + ((cb ^ (nl & 7)) << 4));
                uint32_t bh01[2] = {h0, h1}, bh23[2] = {h2, h3};
                uint32_t bl01[2] = {l0, l1}, bl23[2] = {l2, l3};
                mma16816(acc2[2 * j],     aH, bh01);
                mma16816(acc2[2 * j + 1], aH, bh23);
                mma16816(acc2[2 * j],     aH, bl01);
                mma16816(acc2[2 * j + 1], aH, bl23);
                mma16816(acc2[2 * j],     aL, bh01);
                mma16816(acc2[2 * j + 1], aL, bh23);
            }
        }
        __syncthreads();
    }

    // store attn output tile to g_attn [B*T][512]
    {
        const size_t obase = ((size_t)(b * 1024 + rq)) * 512 + h * 64 + (lane & 3) * 2;
        #pragma unroll
        for (int j = 0; j < 8; j++) {
            *(float2*)(g_attn + obase + 8 * j)                    = make_float2(acc2[j][0], acc2[j][1]);
            *(float2*)(g_attn + obase + 8 * j + (size_t)8 * 512)  = make_float2(acc2[j][2], acc2[j][3]);
        }
    }
}

// ---------------------------------------------------------------------------
extern "C" void kernel_launch(void* const* d_in, const int* in_sizes, int n_in,
                              void* d_out, int out_size)
{
    (void)in_sizes; (void)n_in; (void)out_size;
    const float* q  = (const float*)d_in[0];
    const float* k  = (const float*)d_in[1];
    const float* v  = (const float*)d_in[2];
    const float* Wq = (const float*)d_in[3];
    const float* Wk = (const float*)d_in[4];
    const float* Wv = (const float*)d_in[5];
    const float* Wo = (const float*)d_in[6];

    float* out    = (float*)d_out;
    float* attn_w = out + (size_t)B_ * T_ * D_;

    float *p_qh, *p_kh, *p_vh, *p_attn, *p_q2, *p_k2;
    __nv_bfloat16 *p_sA, *p_sW, *p_sQ, *p_sK, *p_sV;
    cudaGetSymbolAddress((void**)&p_qh,   g_qh);
    cudaGetSymbolAddress((void**)&p_kh,   g_kh);
    cudaGetSymbolAddress((void**)&p_vh,   g_vh);
    cudaGetSymbolAddress((void**)&p_attn, g_attn);
    cudaGetSymbolAddress((void**)&p_sA,   g_sA);
    cudaGetSymbolAddress((void**)&p_sW,   g_sW);
    cudaGetSymbolAddress((void**)&p_sQ,   g_sQ);
    cudaGetSymbolAddress((void**)&p_sK,   g_sK);
    cudaGetSymbolAddress((void**)&p_sV,   g_sV);
    cudaGetSymbolAddress((void**)&p_q2,   g_q2);
    cudaGetSymbolAddress((void**)&p_k2,   g_k2);

    cudaFuncSetAttribute(gemm_mma, cudaFuncAttributeMaxDynamicSharedMemorySize, 65536);
    cudaFuncSetAttribute(attn_mma, cudaFuncAttributeMaxDynamicSharedMemorySize, AT_SMEM);

    const dim3 gsplit(4096), bsplit(256);
    const dim3 gwt(16, 16), bwt(32, 32);
    const dim3 ggemm(4, 64), bgemm(256);

    // Projections (validated mma.sync path)
    split_act<<<gsplit, bsplit>>>(q, p_sA);
    split_wt<<<gwt, bwt>>>(Wq, p_sW);
    gemm_mma<<<ggemm, bgemm, 65536>>>(p_sA, p_sW, p_qh);
    split_act<<<gsplit, bsplit>>>(k, p_sA);
    split_wt<<<gwt, bwt>>>(Wk, p_sW);
    gemm_mma<<<ggemm, bgemm, 65536>>>(p_sA, p_sW, p_kh);
    split_act<<<gsplit, bsplit>>>(v, p_sA);
    split_wt<<<gwt, bwt>>>(Wv, p_sW);
    gemm_mma<<<ggemm, bgemm, 65536>>>(p_sA, p_sW, p_vh);

    // Attention preprocessing (per-head splits + norms)
    split_qk<<<dim3(256, H_, B_), 256>>>(p_qh, p_sQ, p_q2, 0);
    split_qk<<<dim3(256, H_, B_), 256>>>(p_kh, p_sK, p_k2, 1);
    split_v<<<dim3(32, 16, B_), dim3(32, 32)>>>(p_vh, p_sV);

    // Fused tensor-core attention (writes attn_w and g_attn)
    attn_mma<<<dim3(T_ / 128, H_, B_), 256, AT_SMEM>>>(attn_w);

    // Output projection
    split_act<<<gsplit, bsplit>>>(p_attn, p_sA);
    split_wt<<<gwt, bwt>>>(Wo, p_sW);
    gemm_mma<<<ggemm, bgemm, 65536>>>(p_sA, p_sW, out);
}

// round 15
// speedup vs baseline: 2.2322x; 1.2258x over previous
#include <cuda_runtime.h>
#include <cuda_bf16.h>
#include <cstdint>
#include <cstddef>

#define B_  8
#define T_  1024
#define D_  512
#define H_  8
#define KD_ 64
#define HK_ 512
#define KSPL 1536      // 3 * 512 (hi|lo|hi split-K for projection GEMMs)

// Scratch (device globals: allocation-free, graph-capture safe).
__device__ float g_qh[(size_t)B_ * T_ * HK_];
__device__ float g_kh[(size_t)B_ * T_ * HK_];
__device__ float g_vh[(size_t)B_ * T_ * HK_];
__device__ float g_attn[(size_t)B_ * T_ * HK_];
__device__ __nv_bfloat16 g_sA[(size_t)B_ * T_ * KSPL];
__device__ __nv_bfloat16 g_sW[(size_t)HK_ * KSPL];
__device__ __nv_bfloat16 g_sQ[(size_t)B_ * H_ * T_ * 192];
__device__ __nv_bfloat16 g_sK[(size_t)B_ * H_ * T_ * 192];
__device__ __nv_bfloat16 g_sV[(size_t)B_ * H_ * 128 * T_];
__device__ float g_q2[(size_t)B_ * H_ * T_];
__device__ float g_k2[(size_t)B_ * H_ * T_];

// ---------------------------------------------------------------------------
__device__ __forceinline__ uint32_t smem_u32(const void* p) {
    uint32_t a;
    asm("{ .reg .u64 t; cvta.to.shared.u64 t, %1; cvt.u32.u64 %0, t; }" : "=r"(a) : "l"(p));
    return a;
}
__device__ __forceinline__ void ldsm4(uint32_t& r0, uint32_t& r1, uint32_t& r2, uint32_t& r3,
                                      uint32_t addr) {
    asm volatile("ldmatrix.sync.aligned.m8n8.x4.shared.b16 {%0,%1,%2,%3}, [%4];"
                 : "=r"(r0), "=r"(r1), "=r"(r2), "=r"(r3) : "r"(addr));
}
__device__ __forceinline__ void mma16816(float* d, const uint32_t* a, const uint32_t* b) {
    asm volatile(
        "mma.sync.aligned.m16n8k16.row.col.f32.bf16.bf16.f32 "
        "{%0,%1,%2,%3}, {%4,%5,%6,%7}, {%8,%9}, {%0,%1,%2,%3};"
        : "+f"(d[0]), "+f"(d[1]), "+f"(d[2]), "+f"(d[3])
        : "r"(a[0]), "r"(a[1]), "r"(a[2]), "r"(a[3]), "r"(b[0]), "r"(b[1]));
}
__device__ __forceinline__ void cpasync16(uint32_t dst, const void* src) {
    asm volatile("cp.async.cg.shared.global [%0], [%1], 16;" :: "r"(dst), "l"(src));
}
__device__ __forceinline__ uint32_t packbf(float lo, float hi) {
    uint32_t r;
    asm("cvt.rn.bf16x2.f32 %0, %1, %2;" : "=r"(r) : "f"(hi), "f"(lo));
    return r;
}
__device__ __forceinline__ void split1(float x, uint16_t& h, uint16_t& l) {
    __nv_bfloat16 bh = __float2bfloat16_rn(x);
    float r = x - __bfloat162float(bh);
    __nv_bfloat16 bl = __float2bfloat16_rn(r);
    h = __bfloat16_as_ushort(bh);
    l = __bfloat16_as_ushort(bl);
}

// ---------------------------------------------------------------------------
__global__ __launch_bounds__(256) void split_act(const float* __restrict__ X,
                                                 __nv_bfloat16* __restrict__ Y) {
    size_t i = (size_t)blockIdx.x * 256 + threadIdx.x;
    float4 v = ((const float4*)X)[i];
    size_t row = i >> 7;
    int col = (int)((i & 127) << 2);
    uint16_t h0, h1, h2, h3, l0, l1, l2, l3;
    split1(v.x, h0, l0); split1(v.y, h1, l1); split1(v.z, h2, l2); split1(v.w, h3, l3);
    uint2 hp, lp;
    hp.x = (uint32_t)h0 | ((uint32_t)h1 << 16);
    hp.y = (uint32_t)h2 | ((uint32_t)h3 << 16);
    lp.x = (uint32_t)l0 | ((uint32_t)l1 << 16);
    lp.y = (uint32_t)l2 | ((uint32_t)l3 << 16);
    __nv_bfloat16* yr = Y + row * KSPL;
    *(uint2*)(yr + col)        = hp;
    *(uint2*)(yr + 512 + col)  = lp;
    *(uint2*)(yr + 1024 + col) = hp;
}

__global__ __launch_bounds__(1024) void split_wt(const float* __restrict__ W,
                                                 __nv_bfloat16* __restrict__ Yt) {
    __shared__ float t[32][33];
    const int tx = threadIdx.x, ty = threadIdx.y;
    const int n0 = blockIdx.x * 32, k0 = blockIdx.y * 32;
    t[ty][tx] = W[(size_t)(k0 + ty) * 512 + n0 + tx];
    __syncthreads();
    float x = t[tx][ty];
    uint16_t h, l; split1(x, h, l);
    uint16_t* yr = (uint16_t*)(Yt + (size_t)(n0 + ty) * KSPL);
    yr[k0 + tx]        = h;
    yr[512 + k0 + tx]  = h;
    yr[1024 + k0 + tx] = l;
}

// ---------------------------------------------------------------------------
#define NCH 24

__global__ __launch_bounds__(256) void gemm_mma(
    const __nv_bfloat16* __restrict__ A,
    const __nv_bfloat16* __restrict__ Bt,
    float* __restrict__ C)
{
    extern __shared__ char sm[];
    const uint32_t smb = smem_u32(sm);
    const int tid = threadIdx.x, lane = tid & 31, wid = tid >> 5;
    const int wm = (wid >> 2) * 64;
    const int wn = (wid & 3) * 32;
    const int tm = blockIdx.y, tn = blockIdx.x;

    const __nv_bfloat16* Ag = A  + (size_t)(tm * 128) * KSPL;
    const __nv_bfloat16* Bg = Bt + (size_t)(tn * 128) * KSPL;

    float acc[4][4][4];
    #pragma unroll
    for (int i = 0; i < 4; i++)
        #pragma unroll
        for (int j = 0; j < 4; j++)
            #pragma unroll
            for (int r = 0; r < 4; r++) acc[i][j][r] = 0.f;

    {
        #pragma unroll
        for (int it = 0; it < 4; it++) {
            int u = tid + it * 256, row = u >> 3, c = u & 7;
            uint32_t d = (uint32_t)(row * 128 + ((c ^ (row & 7)) << 4));
            cpasync16(smb + d,           Ag + (size_t)row * KSPL + c * 8);
            cpasync16(smb + 32768 + d,   Bg + (size_t)row * KSPL + c * 8);
        }
        asm volatile("cp.async.commit_group;");
    }

    for (int ch = 0; ch < NCH; ch++) {
        const int buf = ch & 1;
        if (ch + 1 < NCH) {
            const int nb = (ch + 1) & 1;
            const int ko = (ch + 1) * 64;
            #pragma unroll
            for (int it = 0; it < 4; it++) {
                int u = tid + it * 256, row = u >> 3, c = u & 7;
                uint32_t d = (uint32_t)(nb * 16384 + row * 128 + ((c ^ (row & 7)) << 4));
                cpasync16(smb + d,         Ag + (size_t)row * KSPL + ko + c * 8);
                cpasync16(smb + 32768 + d, Bg + (size_t)row * KSPL + ko + c * 8);
            }
            asm volatile("cp.async.commit_group;");
            asm volatile("cp.async.wait_group 1;");
        } else {
            asm volatile("cp.async.wait_group 0;");
        }
        __syncthreads();

        const uint32_t sA = smb + buf * 16384;
        const uint32_t sB = smb + 32768 + buf * 16384;

        #pragma unroll
        for (int ks = 0; ks < 4; ks++) {
            const int c0 = ks * 2;
            uint32_t aF[4][4], bF[4][2];
            #pragma unroll
            for (int i = 0; i < 4; i++) {
                int m = wm + i * 16 + ((lane >> 3) & 1) * 8 + (lane & 7);
                int c = c0 + (lane >> 4);
                ldsm4(aF[i][0], aF[i][1], aF[i][2], aF[i][3],
                      sA + m * 128 + ((c ^ (m & 7)) << 4));
            }
            #pragma unroll
            for (int jj = 0; jj < 2; jj++) {
                int n = wn + jj * 16 + ((lane >> 4)) * 8 + (lane & 7);
                int c = c0 + ((lane >> 3) & 1);
                uint32_t r0, r1, r2, r3;
                ldsm4(r0, r1, r2, r3, sB + n * 128 + ((c ^ (n & 7)) << 4));
                bF[jj * 2 + 0][0] = r0; bF[jj * 2 + 0][1] = r1;
                bF[jj * 2 + 1][0] = r2; bF[jj * 2 + 1][1] = r3;
            }
            #pragma unroll
            for (int i = 0; i < 4; i++)
                #pragma unroll
                for (int j = 0; j < 4; j++)
                    mma16816(acc[i][j], aF[i], bF[j]);
        }
        __syncthreads();
    }

    #pragma unroll
    for (int i = 0; i < 4; i++) {
        int row0 = tm * 128 + wm + i * 16 + (lane >> 2);
        #pragma unroll
        for (int j = 0; j < 4; j++) {
            int col = tn * 128 + wn + j * 8 + (lane & 3) * 2;
            *(float2*)(C + (size_t)row0 * 512 + col)       = make_float2(acc[i][j][0], acc[i][j][1]);
            *(float2*)(C + (size_t)(row0 + 8) * 512 + col) = make_float2(acc[i][j][2], acc[i][j][3]);
        }
    }
}

// ---------------------------------------------------------------------------
__global__ __launch_bounds__(256) void split_qk(const float* __restrict__ X,
                                                __nv_bfloat16* __restrict__ Y,
                                                float* __restrict__ sq, int kmode) {
    __shared__ float red[4][64];
    const int b = blockIdx.z, h = blockIdx.y;
    const int tr = threadIdx.x >> 6, dh = threadIdx.x & 63;
    const int t = blockIdx.x * 4 + tr;
    float x = X[((size_t)(b * 1024 + t)) * 512 + h * 64 + dh];
    uint16_t hi, lo; split1(x, hi, lo);
    uint16_t* yr = (uint16_t*)Y + ((size_t)((b * 8 + h) * 1024 + t)) * 192;
    yr[dh] = hi;
    if (kmode) { yr[64 + dh] = hi; yr[128 + dh] = lo; }
    else       { yr[64 + dh] = lo; yr[128 + dh] = hi; }
    red[tr][dh] = x * x;
    __syncthreads();
    if (dh == 0) {
        float s = 0.f;
        #pragma unroll 8
        for (int i = 0; i < 64; i++) s += red[tr][i];
        sq[(size_t)(b * 8 + h) * 1024 + t] = s;
    }
}

__global__ void split_v(const float* __restrict__ X, __nv_bfloat16* __restrict__ Y) {
    __shared__ float t32[32][33];
    const int tx = threadIdx.x, ty = threadIdx.y;
    const int Tb = blockIdx.x * 32, Cb = blockIdx.y * 32, b = blockIdx.z;
    t32[ty][tx] = X[((size_t)(b * 1024 + Tb + ty)) * 512 + Cb + tx];
    __syncthreads();
    float val = t32[tx][ty];
    const int col = Cb + ty;
    const int h = col >> 6, dh = col & 63;
    uint16_t hi, lo; split1(val, hi, lo);
    uint16_t* yp = (uint16_t*)Y;
    size_t base = ((size_t)(b * 8 + h) * 128 + dh) * 1024 + Tb + tx;
    yp[base]              = hi;
    yp[base + 64 * 1024]  = lo;
}

// ---------------------------------------------------------------------------
// Fused RBF attention v2: K-block 64, single-buffered K/V, 88KB smem,
// <=128 regs -> 2 CTAs/SM (occupancy hides load latency; exp fused per k16).
// ---------------------------------------------------------------------------
#define SQ_OFF 0
#define SK_OFF 49152
#define SV_OFF 73728
#define AT_SMEM 90112

__global__ __launch_bounds__(256, 2) void attn_mma(float* __restrict__ wout)
{
    extern __shared__ char sm[];
    const uint32_t smb = smem_u32(sm);
    const int tid = threadIdx.x, lane = tid & 31, w = tid >> 5;
    const int qb = blockIdx.x, h = blockIdx.y, b = blockIdx.z;
    const int bh = b * 8 + h;

    const char* Qg = (const char*)(g_sQ + ((size_t)bh * 1024 + qb * 128) * 192);
    const char* Kg = (const char*)(g_sK + (size_t)bh * 1024 * 192);
    const char* Vg = (const char*)(g_sV + (size_t)bh * 128 * 1024);

    // Q load: 128 rows x 24 chunks
    {
        const int row = tid >> 1;
        #pragma unroll
        for (int i = 0; i < 12; i++) {
            int c = (tid & 1) * 12 + i;
            cpasync16(smb + SQ_OFF + row * 384 + ((c ^ (row & 7)) << 4),
                      Qg + (size_t)row * 384 + c * 16);
        }
        asm volatile("cp.async.commit_group;");
    }

    const int rq = qb * 128 + 16 * w + (lane >> 2);
    const float q2a = g_q2[(size_t)bh * 1024 + rq];
    const float q2b = g_q2[(size_t)bh * 1024 + rq + 8];
    const float* k2p = g_k2 + (size_t)bh * 1024;

    float acc2[8][4];
    #pragma unroll
    for (int j = 0; j < 8; j++)
        #pragma unroll
        for (int r = 0; r < 4; r++) acc2[j][r] = 0.f;

    for (int kb = 0; kb < 16; kb++) {
        if (kb > 0) __syncthreads();   // previous iteration done reading K/V
        // K block: 64 rows x 24 chunks (1536 chunks = 256 thr x 6)
        {
            const int row = tid >> 2, cbase = (tid & 3) * 6;
            #pragma unroll
            for (int i = 0; i < 6; i++) {
                int c = cbase + i;
                cpasync16(smb + SK_OFF + row * 384 + ((c ^ (row & 7)) << 4),
                          Kg + (size_t)(kb * 64 + row) * 384 + c * 16);
            }
        }
        // V block: 128 rows x 8 chunks (1024 chunks = 256 thr x 4)
        {
            const int row = tid >> 1, cbase = (tid & 1) * 4;
            #pragma unroll
            for (int i = 0; i < 4; i++) {
                int c = cbase + i;
                cpasync16(smb + SV_OFF + row * 128 + ((c ^ (row & 7)) << 4),
                          Vg + (size_t)row * 2048 + kb * 128 + c * 16);
            }
        }
        asm volatile("cp.async.commit_group;");
        asm volatile("cp.async.wait_group 0;");
        __syncthreads();

        // ---- GEMM1: S[16 x 64] over K'=192 ----
        float sfr[8][4];
        #pragma unroll
        for (int f = 0; f < 8; f++)
            #pragma unroll
            for (int r = 0; r < 4; r++) sfr[f][r] = 0.f;

        #pragma unroll
        for (int ks = 0; ks < 12; ks++) {
            uint32_t a[4];
            {
                int m = 16 * w + (lane & 7) + ((lane >> 3) & 1) * 8;
                int c = 2 * ks + (lane >> 4);
                ldsm4(a[0], a[1], a[2], a[3], smb + SQ_OFF + m * 384 + ((c ^ (m & 7)) << 4));
            }
            #pragma unroll
            for (int j = 0; j < 4; j++) {
                int n = j * 16 + ((lane >> 4)) * 8 + (lane & 7);
                int c = 2 * ks + ((lane >> 3) & 1);
                uint32_t r0, r1, r2, r3;
                ldsm4(r0, r1, r2, r3, smb + SK_OFF + n * 384 + ((c ^ (n & 7)) << 4));
                uint32_t b01[2] = {r0, r1}, b23[2] = {r2, r3};
                mma16816(sfr[2 * j],     a, b01);
                mma16816(sfr[2 * j + 1], a, b23);
            }
        }

        // ---- fused exp + GEMM2, one k16 step at a time ----
        const size_t wbase = ((size_t)bh * 1024 + rq) * 1024 + kb * 64 + (lane & 3) * 2;
        #pragma unroll
        for (int s = 0; s < 4; s++) {
            uint32_t aH[4], aL[4];
            #pragma unroll
            for (int half = 0; half < 2; half++) {
                const int c = 2 * s + half;
                const int colk = kb * 64 + 8 * c + (lane & 3) * 2;
                const float k2x = k2p[colk], k2y = k2p[colk + 1];
                float w0 = __expf(fmaf(2.f, sfr[c][0], -(q2a + k2x)));
                float w1 = __expf(fmaf(2.f, sfr[c][1], -(q2a + k2y)));
                float w2 = __expf(fmaf(2.f, sfr[c][2], -(q2b + k2x)));
                float w3 = __expf(fmaf(2.f, sfr[c][3], -(q2b + k2y)));
                *(float2*)(wout + wbase + 8 * c)                    = make_float2(w0, w1);
                *(float2*)(wout + wbase + 8 * c + (size_t)8 * 1024) = make_float2(w2, w3);
                uint32_t h01 = packbf(w0, w1);
                uint32_t h23 = packbf(w2, w3);
                float l0 = w0 - __uint_as_float(h01 << 16);
                float l1 = w1 - __uint_as_float(h01 & 0xFFFF0000u);
                float l2 = w2 - __uint_as_float(h23 << 16);
                float l3 = w3 - __uint_as_float(h23 & 0xFFFF0000u);
                aH[2 * half + 0] = h01; aH[2 * half + 1] = h23;
                aL[2 * half + 0] = packbf(l0, l1);
                aL[2 * half + 1] = packbf(l2, l3);
            }
            #pragma unroll
            for (int j = 0; j < 4; j++) {
                int nh = j * 16 + ((lane >> 4)) * 8 + (lane & 7);
                int cb = 2 * s + ((lane >> 3) & 1);
                uint32_t h0, h1, h2, h3, l0, l1, l2, l3;
                ldsm4(h0, h1, h2, h3, smb + SV_OFF + nh * 128 + ((cb ^ (nh & 7)) << 4));
                int nl = nh + 64;
                ldsm4(l0, l1, l2, l3, smb + SV_OFF + nl * 128 + ((cb ^ (nl & 7)) << 4));
                uint32_t bh01[2] = {h0, h1}, bh23[2] = {h2, h3};
                uint32_t bl01[2] = {l0, l1}, bl23[2] = {l2, l3};
                mma16816(acc2[2 * j],     aH, bh01);
                mma16816(acc2[2 * j + 1], aH, bh23);
                mma16816(acc2[2 * j],     aH, bl01);
                mma16816(acc2[2 * j + 1], aH, bl23);
                mma16816(acc2[2 * j],     aL, bh01);
                mma16816(acc2[2 * j + 1], aL, bh23);
            }
        }
    }

    // store attn output tile to g_attn [B*T][512]
    {
        const size_t obase = ((size_t)(b * 1024 + rq)) * 512 + h * 64 + (lane & 3) * 2;
        #pragma unroll
        for (int j = 0; j < 8; j++) {
            *(float2*)(g_attn + obase + 8 * j)                    = make_float2(acc2[j][0], acc2[j][1]);
            *(float2*)(g_attn + obase + 8 * j + (size_t)8 * 512)  = make_float2(acc2[j][2], acc2[j][3]);
        }
    }
}

// ---------------------------------------------------------------------------
extern "C" void kernel_launch(void* const* d_in, const int* in_sizes, int n_in,
                              void* d_out, int out_size)
{
    (void)in_sizes; (void)n_in; (void)out_size;
    const float* q  = (const float*)d_in[0];
    const float* k  = (const float*)d_in[1];
    const float* v  = (const float*)d_in[2];
    const float* Wq = (const float*)d_in[3];
    const float* Wk = (const float*)d_in[4];
    const float* Wv = (const float*)d_in[5];
    const float* Wo = (const float*)d_in[6];

    float* out    = (float*)d_out;
    float* attn_w = out + (size_t)B_ * T_ * D_;

    float *p_qh, *p_kh, *p_vh, *p_attn, *p_q2, *p_k2;
    __nv_bfloat16 *p_sA, *p_sW, *p_sQ, *p_sK, *p_sV;
    cudaGetSymbolAddress((void**)&p_qh,   g_qh);
    cudaGetSymbolAddress((void**)&p_kh,   g_kh);
    cudaGetSymbolAddress((void**)&p_vh,   g_vh);
    cudaGetSymbolAddress((void**)&p_attn, g_attn);
    cudaGetSymbolAddress((void**)&p_sA,   g_sA);
    cudaGetSymbolAddress((void**)&p_sW,   g_sW);
    cudaGetSymbolAddress((void**)&p_sQ,   g_sQ);
    cudaGetSymbolAddress((void**)&p_sK,   g_sK);
    cudaGetSymbolAddress((void**)&p_sV,   g_sV);
    cudaGetSymbolAddress((void**)&p_q2,   g_q2);
    cudaGetSymbolAddress((void**)&p_k2,   g_k2);

    cudaFuncSetAttribute(gemm_mma, cudaFuncAttributeMaxDynamicSharedMemorySize, 65536);
    cudaFuncSetAttribute(attn_mma, cudaFuncAttributeMaxDynamicSharedMemorySize, AT_SMEM);

    const dim3 gsplit(4096), bsplit(256);
    const dim3 gwt(16, 16), bwt(32, 32);
    const dim3 ggemm(4, 64), bgemm(256);

    split_act<<<gsplit, bsplit>>>(q, p_sA);
    split_wt<<<gwt, bwt>>>(Wq, p_sW);
    gemm_mma<<<ggemm, bgemm, 65536>>>(p_sA, p_sW, p_qh);
    split_act<<<gsplit, bsplit>>>(k, p_sA);
    split_wt<<<gwt, bwt>>>(Wk, p_sW);
    gemm_mma<<<ggemm, bgemm, 65536>>>(p_sA, p_sW, p_kh);
    split_act<<<gsplit, bsplit>>>(v, p_sA);
    split_wt<<<gwt, bwt>>>(Wv, p_sW);
    gemm_mma<<<ggemm, bgemm, 65536>>>(p_sA, p_sW, p_vh);

    split_qk<<<dim3(256, H_, B_), 256>>>(p_qh, p_sQ, p_q2, 0);
    split_qk<<<dim3(256, H_, B_), 256>>>(p_kh, p_sK, p_k2, 1);
    split_v<<<dim3(32, 16, B_), dim3(32, 32)>>>(p_vh, p_sV);

    attn_mma<<<dim3(T_ / 128, H_, B_), 256, AT_SMEM>>>(attn_w);

    split_act<<<gsplit, bsplit>>>(p_attn, p_sA);
    split_wt<<<gwt, bwt>>>(Wo, p_sW);
    gemm_mma<<<ggemm, bgemm, 65536>>>(p_sA, p_sW, out);
}